// round 16
// baseline (speedup 1.0000x reference)
#include <cuda_runtime.h>
#include <cuda_fp16.h>
#include <cstdint>

#define NTOK 8192
#define HEADS 12
#define ROWSTRIDE 768   // HEADS*64 floats between consecutive tokens

__device__ float g_denom[2 * HEADS * 64];
__device__ float g_partial[2 * HEADS * 8 * 64];

// ---------------------------------------------------------------------------
// helpers
// ---------------------------------------------------------------------------
__device__ __forceinline__ float fast_exp2(float x) {
    float y; asm("ex2.approx.ftz.f32 %0, %1;" : "=f"(y) : "f"(x)); return y;
}
__device__ __forceinline__ uint32_t packh2(float lo, float hi) {
    uint32_t r;
    asm("cvt.rn.f16x2.f32 %0, %1, %2;" : "=r"(r) : "f"(hi), "f"(lo));
    return r;
}
__device__ __forceinline__ float2 unpackh2(uint32_t p) {
    __half2 h = *reinterpret_cast<__half2*>(&p);
    return __half22float2(h);
}
__device__ __forceinline__ uint32_t smem_u32(const void* p) {
    uint32_t a;
    asm("{ .reg .u64 t; cvta.to.shared.u64 t, %1; cvt.u32.u64 %0, t; }" : "=r"(a) : "l"(p));
    return a;
}
__device__ __forceinline__ void ldsm4(uint32_t r[4], uint32_t addr) {
    asm volatile("ldmatrix.sync.aligned.m8n8.x4.shared.b16 {%0,%1,%2,%3}, [%4];"
                 : "=r"(r[0]), "=r"(r[1]), "=r"(r[2]), "=r"(r[3]) : "r"(addr));
}
__device__ __forceinline__ void ldsm4t(uint32_t r[4], uint32_t addr) {
    asm volatile("ldmatrix.sync.aligned.m8n8.x4.trans.shared.b16 {%0,%1,%2,%3}, [%4];"
                 : "=r"(r[0]), "=r"(r[1]), "=r"(r[2]), "=r"(r[3]) : "r"(addr));
}
__device__ __forceinline__ void mma16816(float d[4], const uint32_t a[4],
                                         uint32_t b0, uint32_t b1, const float c[4]) {
    asm volatile(
        "mma.sync.aligned.m16n8k16.row.col.f32.f16.f16.f32 "
        "{%0,%1,%2,%3},{%4,%5,%6,%7},{%8,%9},{%10,%11,%12,%13};"
        : "=f"(d[0]), "=f"(d[1]), "=f"(d[2]), "=f"(d[3])
        : "r"(a[0]), "r"(a[1]), "r"(a[2]), "r"(a[3]), "r"(b0), "r"(b1),
          "f"(c[0]), "f"(c[1]), "f"(c[2]), "f"(c[3]));
}
__device__ __forceinline__ void cp_async16(uint32_t dst, const void* src) {
    asm volatile("cp.async.cg.shared.global [%0], [%1], 16;" :: "r"(dst), "l"(src));
}
#define CP_COMMIT() asm volatile("cp.async.commit_group;" ::: "memory")
#define CP_WAIT(n)  asm volatile("cp.async.wait_group %0;" :: "n"(n) : "memory")

__device__ __forceinline__ float4 lds128f(uint32_t addr) {
    float4 v;
    asm volatile("ld.shared.v4.f32 {%0,%1,%2,%3}, [%4];"
                 : "=f"(v.x), "=f"(v.y), "=f"(v.z), "=f"(v.w) : "r"(addr));
    return v;
}

// swizzled byte offset of (row, 16B-chunk) in a [rows][64 half] tile (128B/row)
#define SWB(row, c8) (((uint32_t)(row) << 7) + ((((uint32_t)(c8)) ^ ((uint32_t)(row) & 7u)) << 4))

// smem layout (per CTA): BLOCK_N = 64 kv rows
#define O_RAWK 0            // 16 KB raw fp32 K tile (64 x 64)
#define O_RAWV 16384        // 16 KB raw fp32 V tile
#define O_BUF  32768        // 2 x 32 KB fp16 buffer sets
#define B_KH 0
#define B_KL 8192
#define B_VH 16384
#define B_VL 24576
#define BUFSZ 32768
#define SMEM_BYTES (32768 + 2 * 32768)   // 96 KB -> 2 CTAs/SM

#define C11 (1.0f / 2048.0f)
#define C22 (C11 * C11)

// convert raw chunk c (K and V) into fp16 buffer set dst; c in [0,1024)
__device__ __forceinline__ void convert_chunk(uint32_t sb, uint32_t dst, int c) {
    const int row = c >> 4, f4 = c & 15;
    const uint32_t o8 = SWB(row, f4 >> 1) + ((uint32_t)(f4 & 1) << 3);
    {
        float4 v = lds128f(sb + O_RAWK + (uint32_t)c * 16);
        uint32_t h0 = packh2(v.x, v.y), h1 = packh2(v.z, v.w);
        float2 f0 = unpackh2(h0), f1 = unpackh2(h1);
        uint32_t l0_ = packh2((v.x - f0.x) * 2048.f, (v.y - f0.y) * 2048.f);
        uint32_t l1_ = packh2((v.z - f1.x) * 2048.f, (v.w - f1.y) * 2048.f);
        asm volatile("st.shared.v2.b32 [%0], {%1,%2};" :: "r"(dst + B_KH + o8), "r"(h0), "r"(h1));
        asm volatile("st.shared.v2.b32 [%0], {%1,%2};" :: "r"(dst + B_KL + o8), "r"(l0_), "r"(l1_));
    }
    {
        float4 v = lds128f(sb + O_RAWV + (uint32_t)c * 16);
        uint32_t h0 = packh2(v.x, v.y), h1 = packh2(v.z, v.w);
        float2 f0 = unpackh2(h0), f1 = unpackh2(h1);
        uint32_t l0_ = packh2((v.x - f0.x) * 2048.f, (v.y - f0.y) * 2048.f);
        uint32_t l1_ = packh2((v.z - f1.x) * 2048.f, (v.w - f1.y) * 2048.f);
        asm volatile("st.shared.v2.b32 [%0], {%1,%2};" :: "r"(dst + B_VH + o8), "r"(h0), "r"(h1));
        asm volatile("st.shared.v2.b32 [%0], {%1,%2};" :: "r"(dst + B_VL + o8), "r"(l0_), "r"(l1_));
    }
}

// issue cp.async (K,V) for raw chunk c; NO commit (caller groups)
__device__ __forceinline__ void issue_chunk(uint32_t sb, int c,
                                            const float* kb, const float* vb,
                                            long rstride) {
    const int row = c >> 4, f4 = c & 15;
    cp_async16(sb + O_RAWK + (uint32_t)c * 16, kb + (long)row * rstride + (f4 << 2));
    cp_async16(sb + O_RAWV + (uint32_t)c * 16, vb + (long)row * rstride + (f4 << 2));
}

// ---------------------------------------------------------------------------
// Kernel 1: scaled-split-fp16 mma.sync flash attention, 2 CTAs/SM.
// CTA = 128 threads = 4 warps, 64 q-rows (16/warp), BLOCK_N = 64, 32 kv tiles.
// Same per-element MMA sequence as R14/R15 (bit-identical numerics).
// ---------------------------------------------------------------------------
__global__ void __launch_bounds__(128) attn_kernel(
    const float* __restrict__ Q,
    const float* __restrict__ K,
    const float* __restrict__ V,
    float* __restrict__ out)
{
    extern __shared__ __align__(16) char smem_raw[];
    const uint32_t sb = smem_u32(smem_raw);
    const uint32_t buf0 = sb + O_BUF;
    const uint32_t buf1 = sb + O_BUF + BUFSZ;

    const int tid  = threadIdx.x;
    const int wid  = tid >> 5;        // 0..3
    const int lane = tid & 31;

    // ---- decode job ----
    const int job = blockIdx.y;
    int g, b, seg, hl;
    if (job < 32)      { g = 0; hl = job & 3;  seg = (job >> 2) & 3; b = job >> 4; }
    else if (job < 48) { int l = job - 32; g = 1; hl = l & 3; seg = (l >> 2) & 1; b = l >> 3; }
    else               { int l = job - 48; g = 2; hl = l & 3; seg = 0;            b = l >> 2; }
    const int r   = 1 << g;
    const int s   = 2048 << g;
    const int off = (g == 2) ? 2 : g;
    const int h   = g * 4 + hl;
    const long rstride = (long)r * ROWSTRIDE;
    const long segbase = ((long)b * NTOK + (long)seg * s + off) * ROWSTRIDE + h * 64;
    const long qbase   = segbase + (long)blockIdx.x * 64 * rstride;

    // ---- prologue: cp.async raw tile 0 (single group; 8 K + 8 V chunks/thread) ----
    {
        const float* kb = K + segbase;
        const float* vb = V + segbase;
        #pragma unroll
        for (int i = 0; i < 8; i++) {
            int c = tid + (i << 7);
            issue_chunk(sb, c, kb, vb, rstride);
        }
        CP_COMMIT();
    }

    // ---- stage Q (pre-scaled) into buf0.KH/KL, extract fragments ----
    // Q tile: 64 rows x 64 d = 1024 chunks; 8 per thread
    const float qs = 0.125f * 1.4426950408889634f;
    #pragma unroll
    for (int i = 0; i < 8; i++) {
        int linear = tid + (i << 7);
        int row = linear >> 4, f4 = linear & 15;
        float4 v = *(const float4*)(Q + qbase + (long)row * rstride + (f4 << 2));
        v.x *= qs; v.y *= qs; v.z *= qs; v.w *= qs;
        uint32_t h0 = packh2(v.x, v.y), h1 = packh2(v.z, v.w);
        float2 f0 = unpackh2(h0), f1 = unpackh2(h1);
        uint32_t l0_ = packh2((v.x - f0.x) * 2048.f, (v.y - f0.y) * 2048.f);
        uint32_t l1_ = packh2((v.z - f1.x) * 2048.f, (v.w - f1.y) * 2048.f);
        uint32_t o8 = SWB(row, f4 >> 1) + ((uint32_t)(f4 & 1) << 3);
        asm volatile("st.shared.v2.b32 [%0], {%1,%2};" :: "r"(buf0 + B_KH + o8), "r"(h0), "r"(h1));
        asm volatile("st.shared.v2.b32 [%0], {%1,%2};" :: "r"(buf0 + B_KL + o8), "r"(l0_), "r"(l1_));
    }
    __syncthreads();

    uint32_t qfh[4][4], qfl[4][4];
    {
        uint32_t row = (uint32_t)(wid * 16 + (lane & 15));
        #pragma unroll
        for (int ks = 0; ks < 4; ks++) {
            uint32_t chunk = (uint32_t)(lane >> 4) + ((uint32_t)ks << 1);
            ldsm4(qfh[ks], buf0 + B_KH + SWB(row, chunk));
            ldsm4(qfl[ks], buf0 + B_KL + SWB(row, chunk));
        }
    }
    __syncthreads();   // all warps read Q before convert overwrites buf0

    // ---- wait raw tile0, convert to buf0, issue tile1 (4 pair-groups) ----
    CP_WAIT(0);
    {
        const float* kb = K + segbase + (long)64 * rstride;
        const float* vb = V + segbase + (long)64 * rstride;
        #pragma unroll
        for (int p = 0; p < 4; p++) {
            int c0 = tid + ((2 * p) << 7);
            int c1 = tid + ((2 * p + 1) << 7);
            convert_chunk(sb, buf0, c0);
            convert_chunk(sb, buf0, c1);
            issue_chunk(sb, c0, kb, vb, rstride);
            issue_chunk(sb, c1, kb, vb, rstride);
            CP_COMMIT();
        }
    }
    __syncthreads();   // buf0 ready

    float oacc[8][4];
    #pragma unroll
    for (int i = 0; i < 8; i++)
        #pragma unroll
        for (int e = 0; e < 4; e++) oacc[i][e] = 0.f;
    float lr0 = 0.f, lr1 = 0.f;

    for (int kt = 0; kt < 32; kt++) {
        const uint32_t cur = (kt & 1) ? buf1 : buf0;
        const uint32_t nxt = (kt & 1) ? buf0 : buf1;
        int nt = (kt + 2 < 32) ? (kt + 2) : 31;
        const float* kb2 = K + segbase + (long)(nt * 64) * rstride;
        const float* vb2 = V + segbase + (long)(nt * 64) * rstride;
        const bool doconv = (kt < 31);

        float ocor[8][4];
        #pragma unroll
        for (int i = 0; i < 8; i++)
            #pragma unroll
            for (int e = 0; e < 4; e++) ocor[i][e] = 0.f;

        // ping-pong GEMM1 accumulator block
        float ablk[2][6][4];
        #pragma unroll
        for (int a = 0; a < 6; a++)
            #pragma unroll
            for (int e = 0; e < 4; e++) ablk[0][a][e] = 0.f;
        {
            uint32_t row = (uint32_t)(lane & 15);
            #pragma unroll
            for (int ks = 0; ks < 4; ks++) {
                uint32_t chunk = (uint32_t)(lane >> 4) + ((uint32_t)ks << 1);
                uint32_t kh[4], kl[4];
                ldsm4(kh, cur + B_KH + SWB(row, chunk));
                ldsm4(kl, cur + B_KL + SWB(row, chunk));
                mma16816(ablk[0][0], qfh[ks], kh[0], kh[2], ablk[0][0]);
                mma16816(ablk[0][1], qfh[ks], kh[1], kh[3], ablk[0][1]);
                mma16816(ablk[0][2], qfh[ks], kl[0], kl[2], ablk[0][2]);
                mma16816(ablk[0][3], qfh[ks], kl[1], kl[3], ablk[0][3]);
                mma16816(ablk[0][2], qfl[ks], kh[0], kh[2], ablk[0][2]);
                mma16816(ablk[0][3], qfl[ks], kh[1], kh[3], ablk[0][3]);
                mma16816(ablk[0][4], qfl[ks], kl[0], kl[2], ablk[0][4]);
                mma16816(ablk[0][5], qfl[ks], kl[1], kl[3], ablk[0][5]);
            }
        }

        #pragma unroll
        for (int j = 0; j < 4; j++) {
            const int pj = j & 1, nj = pj ^ 1;

            // ---- softmax(j) from ablk[pj] ----
            uint32_t pfh[4], pfl[4], pfu[4];
            {
                float s0 = ablk[pj][0][0] + ablk[pj][2][0] * C11 + ablk[pj][4][0] * C22;
                float s1 = ablk[pj][0][1] + ablk[pj][2][1] * C11 + ablk[pj][4][1] * C22;
                float s2 = ablk[pj][0][2] + ablk[pj][2][2] * C11 + ablk[pj][4][2] * C22;
                float s3 = ablk[pj][0][3] + ablk[pj][2][3] * C11 + ablk[pj][4][3] * C22;
                float s4 = ablk[pj][1][0] + ablk[pj][3][0] * C11 + ablk[pj][5][0] * C22;
                float s5 = ablk[pj][1][1] + ablk[pj][3][1] * C11 + ablk[pj][5][1] * C22;
                float s6 = ablk[pj][1][2] + ablk[pj][3][2] * C11 + ablk[pj][5][2] * C22;
                float s7 = ablk[pj][1][3] + ablk[pj][3][3] * C11 + ablk[pj][5][3] * C22;
                float p0 = fast_exp2(s0), p1 = fast_exp2(s1);
                float p2 = fast_exp2(s2), p3 = fast_exp2(s3);
                float p4 = fast_exp2(s4), p5 = fast_exp2(s5);
                float p6 = fast_exp2(s6), p7 = fast_exp2(s7);
                lr0 += (p0 + p1) + (p4 + p5);
                lr1 += (p2 + p3) + (p6 + p7);
                pfh[0] = packh2(p0, p1);
                pfh[1] = packh2(p2, p3);
                pfh[2] = packh2(p4, p5);
                pfh[3] = packh2(p6, p7);
                float2 f;
                float d0, d1;
                f = unpackh2(pfh[0]); d0 = p0 - f.x; d1 = p1 - f.y;
                pfl[0] = packh2(d0 * 2048.f, d1 * 2048.f); pfu[0] = packh2(d0, d1);
                f = unpackh2(pfh[1]); d0 = p2 - f.x; d1 = p3 - f.y;
                pfl[1] = packh2(d0 * 2048.f, d1 * 2048.f); pfu[1] = packh2(d0, d1);
                f = unpackh2(pfh[2]); d0 = p4 - f.x; d1 = p5 - f.y;
                pfl[2] = packh2(d0 * 2048.f, d1 * 2048.f); pfu[2] = packh2(d0, d1);
                f = unpackh2(pfh[3]); d0 = p6 - f.x; d1 = p7 - f.y;
                pfl[3] = packh2(d0 * 2048.f, d1 * 2048.f); pfu[3] = packh2(d0, d1);
            }

            // ---- zero ablk[nj] for GEMM1(j+1) ----
            if (j < 3) {
                #pragma unroll
                for (int a = 0; a < 6; a++)
                    #pragma unroll
                    for (int e = 0; e < 4; e++) ablk[nj][a][e] = 0.f;
            }

            // ---- fused: GEMM1(j+1) ks=i interleaved with GEMM2(j) dp=i ----
            uint32_t nrow = ((uint32_t)(j + 1) << 4) + (uint32_t)(lane & 15);
            uint32_t jr = ((uint32_t)j << 4) + (uint32_t)(lane & 7) + ((((uint32_t)lane >> 3) & 1u) << 3);
            #pragma unroll
            for (int i = 0; i < 4; i++) {
                uint32_t chunk = (uint32_t)(lane >> 4) + ((uint32_t)i << 1);
                if (j < 3) {
                    uint32_t kh[4], kl[4];
                    ldsm4(kh, cur + B_KH + SWB(nrow, chunk));
                    ldsm4(kl, cur + B_KL + SWB(nrow, chunk));
                    mma16816(ablk[nj][0], qfh[i], kh[0], kh[2], ablk[nj][0]);
                    mma16816(ablk[nj][1], qfh[i], kh[1], kh[3], ablk[nj][1]);
                    mma16816(ablk[nj][2], qfh[i], kl[0], kl[2], ablk[nj][2]);
                    mma16816(ablk[nj][3], qfh[i], kl[1], kl[3], ablk[nj][3]);
                    mma16816(ablk[nj][2], qfl[i], kh[0], kh[2], ablk[nj][2]);
                    mma16816(ablk[nj][3], qfl[i], kh[1], kh[3], ablk[nj][3]);
                    mma16816(ablk[nj][4], qfl[i], kl[0], kl[2], ablk[nj][4]);
                    mma16816(ablk[nj][5], qfl[i], kl[1], kl[3], ablk[nj][5]);
                }
                {
                    uint32_t vh[4], vl[4];
                    ldsm4t(vh, cur + B_VH + SWB(jr, chunk));
                    ldsm4t(vl, cur + B_VL + SWB(jr, chunk));
                    mma16816(oacc[2*i],   pfh, vh[0], vh[1], oacc[2*i]);
                    mma16816(oacc[2*i+1], pfh, vh[2], vh[3], oacc[2*i+1]);
                    mma16816(ocor[2*i],   pfh, vl[0], vl[1], ocor[2*i]);
                    mma16816(ocor[2*i+1], pfh, vl[2], vl[3], ocor[2*i+1]);
                    mma16816(ocor[2*i],   pfl, vh[0], vh[1], ocor[2*i]);
                    mma16816(ocor[2*i+1], pfl, vh[2], vh[3], ocor[2*i+1]);
                    mma16816(ocor[2*i],   pfu, vl[0], vl[1], ocor[2*i]);   // == pfl*vu
                    mma16816(ocor[2*i+1], pfu, vl[2], vl[3], ocor[2*i+1]);
                }
            }

            // ---- interleaved: convert chunk pair j of tile kt+1, refill kt+2 ----
            if (doconv) {
                CP_WAIT(3);                        // oldest group = pair j of tile kt+1
                int c0 = tid + ((2 * j) << 7);
                int c1 = tid + ((2 * j + 1) << 7);
                convert_chunk(sb, nxt, c0);
                convert_chunk(sb, nxt, c1);
                issue_chunk(sb, c0, kb2, vb2, rstride);
                issue_chunk(sb, c1, kb2, vb2, rstride);
                CP_COMMIT();
            }
        }

        // fold correction into main accumulator (per tile; same as before)
        #pragma unroll
        for (int i = 0; i < 8; i++)
            #pragma unroll
            for (int e = 0; e < 4; e++)
                oacc[i][e] = fmaf(ocor[i][e], C11, oacc[i][e]);

        __syncthreads();   // all warps done with cur before next iter overwrites it
    }
    CP_WAIT(0);            // retire trailing dummy groups before exit

    // ---- epilogue: reduce l across quad, normalize, write ----
    lr0 += __shfl_xor_sync(0xffffffffu, lr0, 1);
    lr0 += __shfl_xor_sync(0xffffffffu, lr0, 2);
    lr1 += __shfl_xor_sync(0xffffffffu, lr1, 1);
    lr1 += __shfl_xor_sync(0xffffffffu, lr1, 2);
    const float inv0 = 1.f / lr0;
    const float inv1 = 1.f / lr1;

    const int gq = lane >> 2, t4 = lane & 3;
    float* r0p = out + qbase + (long)(wid * 16 + gq) * rstride;
    float* r1p = out + qbase + (long)(wid * 16 + gq + 8) * rstride;
    #pragma unroll
    for (int dt = 0; dt < 8; dt++) {
        float2 w0 = make_float2(oacc[dt][0] * inv0, oacc[dt][1] * inv0);
        float2 w1 = make_float2(oacc[dt][2] * inv1, oacc[dt][3] * inv1);
        *(float2*)(r0p + dt * 8 + 2 * t4) = w0;
        *(float2*)(r1p + dt * 8 + 2 * t4) = w1;
    }
}

// ---------------------------------------------------------------------------
// Kernel 2a: per-(b,h) partial sums over covered positions (8 parts).
// ---------------------------------------------------------------------------
__global__ void __launch_bounds__(512) denom_partial(const float* __restrict__ out)
{
    __shared__ float red[512];
    const int bh   = blockIdx.x;      // 0..23
    const int part = blockIdx.y;      // 0..7
    const int b  = bh / HEADS;
    const int h  = bh % HEADS;
    const int g  = h >> 2;
    const int r  = 1 << g;
    const int off = (g == 2) ? 2 : g;

    const int tid   = threadIdx.x;
    const int d     = tid & 63;
    const int slice = tid >> 6;            // 0..7
    const int lanei = part * 8 + slice;    // 0..63
    const int count = NTOK >> g;

    const float* p = out + ((long)b * NTOK + off) * ROWSTRIDE + h * 64 + d;
    float acc = 0.f;
    for (int t = lanei; t < count; t += 64)
        acc += p[(long)t * r * ROWSTRIDE];

    red[tid] = acc;
    __syncthreads();
    if (slice == 0) {
        float sum = red[d];
        #pragma unroll
        for (int k = 1; k < 8; k++) sum += red[k * 64 + d];
        g_partial[(bh * 8 + part) * 64 + d] = sum;
    }
}

// ---------------------------------------------------------------------------
// Kernel 2b: combine partials into g_denom.
// ---------------------------------------------------------------------------
__global__ void __launch_bounds__(64) denom_combine()
{
    const int bh = blockIdx.x;
    const int d  = threadIdx.x;
    float s = 0.f;
    #pragma unroll
    for (int p = 0; p < 8; p++)
        s += g_partial[(bh * 8 + p) * 64 + d];
    g_denom[bh * 64 + d] = s;
}

// ---------------------------------------------------------------------------
// Kernel 3: final normalize + zero uncovered positions (float4).
// ---------------------------------------------------------------------------
__global__ void __launch_bounds__(256) norm_kernel(float4* __restrict__ out4)
{
    const long total4 = (long)2 * NTOK * HEADS * 16;
    long i4 = (long)blockIdx.x * 256 + threadIdx.x;
    if (i4 >= total4) return;

    int  dq = (int)(i4 & 15);
    long t = i4 >> 4;
    int  h = (int)(t % HEADS); t /= HEADS;
    int  n = (int)(t % NTOK);
    int  b = (int)(t / NTOK);

    int g   = h >> 2;
    int r   = 1 << g;
    int off = (g == 2) ? 2 : g;

    float4 v = make_float4(0.f, 0.f, 0.f, 0.f);
    if ((n & (r - 1)) == off) {
        float4 x = out4[i4];
        const float* dn = g_denom + (b * HEADS + h) * 64 + dq * 4;
        v.x = x.x / (dn[0] * 3.0f);
        v.y = x.y / (dn[1] * 3.0f);
        v.z = x.z / (dn[2] * 3.0f);
        v.w = x.w / (dn[3] * 3.0f);
    }
    out4[i4] = v;
}

// ---------------------------------------------------------------------------
extern "C" void kernel_launch(void* const* d_in, const int* in_sizes, int n_in,
                              void* d_out, int out_size)
{
    const float* Q = (const float*)d_in[0];
    const float* K = (const float*)d_in[1];
    const float* V = (const float*)d_in[2];
    float* out = (float*)d_out;

    static int configured = 0;
    if (!configured) {
        cudaFuncSetAttribute(attn_kernel,
                             cudaFuncAttributeMaxDynamicSharedMemorySize, SMEM_BYTES);
        configured = 1;
    }

    attn_kernel<<<dim3(32, 56), 128, SMEM_BYTES>>>(Q, K, V, out);
    denom_partial<<<dim3(2 * HEADS, 8), 512>>>(out);
    denom_combine<<<2 * HEADS, 64>>>();

    const long total4 = (long)2 * NTOK * HEADS * 16;
    int blocks = (int)((total4 + 255) / 256);
    norm_kernel<<<blocks, 256>>>((float4*)out);
}

// round 17
// speedup vs baseline: 1.3186x; 1.3186x over previous
#include <cuda_runtime.h>
#include <cuda_fp16.h>
#include <cstdint>

#define NTOK 8192
#define HEADS 12
#define ROWSTRIDE 768   // HEADS*64 floats between consecutive tokens

__device__ float g_denom[2 * HEADS * 64];
__device__ float g_partial[2 * HEADS * 8 * 64];

// ---------------------------------------------------------------------------
// helpers
// ---------------------------------------------------------------------------
__device__ __forceinline__ float fast_exp2(float x) {
    float y; asm("ex2.approx.ftz.f32 %0, %1;" : "=f"(y) : "f"(x)); return y;
}
__device__ __forceinline__ uint32_t packh2(float lo, float hi) {
    uint32_t r;
    asm("cvt.rn.f16x2.f32 %0, %1, %2;" : "=r"(r) : "f"(hi), "f"(lo));
    return r;
}
__device__ __forceinline__ float2 unpackh2(uint32_t p) {
    __half2 h = *reinterpret_cast<__half2*>(&p);
    return __half22float2(h);
}
__device__ __forceinline__ uint32_t smem_u32(const void* p) {
    uint32_t a;
    asm("{ .reg .u64 t; cvta.to.shared.u64 t, %1; cvt.u32.u64 %0, t; }" : "=r"(a) : "l"(p));
    return a;
}
__device__ __forceinline__ void ldsm4(uint32_t r[4], uint32_t addr) {
    asm volatile("ldmatrix.sync.aligned.m8n8.x4.shared.b16 {%0,%1,%2,%3}, [%4];"
                 : "=r"(r[0]), "=r"(r[1]), "=r"(r[2]), "=r"(r[3]) : "r"(addr));
}
__device__ __forceinline__ void ldsm4t(uint32_t r[4], uint32_t addr) {
    asm volatile("ldmatrix.sync.aligned.m8n8.x4.trans.shared.b16 {%0,%1,%2,%3}, [%4];"
                 : "=r"(r[0]), "=r"(r[1]), "=r"(r[2]), "=r"(r[3]) : "r"(addr));
}
__device__ __forceinline__ void mma16816(float d[4], const uint32_t a[4],
                                         uint32_t b0, uint32_t b1, const float c[4]) {
    asm volatile(
        "mma.sync.aligned.m16n8k16.row.col.f32.f16.f16.f32 "
        "{%0,%1,%2,%3},{%4,%5,%6,%7},{%8,%9},{%10,%11,%12,%13};"
        : "=f"(d[0]), "=f"(d[1]), "=f"(d[2]), "=f"(d[3])
        : "r"(a[0]), "r"(a[1]), "r"(a[2]), "r"(a[3]), "r"(b0), "r"(b1),
          "f"(c[0]), "f"(c[1]), "f"(c[2]), "f"(c[3]));
}
__device__ __forceinline__ void cp_async16(uint32_t dst, const void* src) {
    asm volatile("cp.async.cg.shared.global [%0], [%1], 16;" :: "r"(dst), "l"(src));
}
#define CP_COMMIT() asm volatile("cp.async.commit_group;" ::: "memory")
#define CP_WAIT(n)  asm volatile("cp.async.wait_group %0;" :: "n"(n) : "memory")

__device__ __forceinline__ float4 lds128f(uint32_t addr) {
    float4 v;
    asm volatile("ld.shared.v4.f32 {%0,%1,%2,%3}, [%4];"
                 : "=f"(v.x), "=f"(v.y), "=f"(v.z), "=f"(v.w) : "r"(addr));
    return v;
}

// swizzled byte offset of (row, 16B-chunk) in a [rows][64 half] tile (128B/row)
#define SWB(row, c8) (((uint32_t)(row) << 7) + ((((uint32_t)(c8)) ^ ((uint32_t)(row) & 7u)) << 4))

// smem layout
#define O_RAWK 0            // 32 KB raw fp32 K tile
#define O_RAWV 32768        // 32 KB raw fp32 V tile
#define O_BUF  65536        // 2 x 64 KB fp16 buffer sets
#define B_KH 0
#define B_KL 16384
#define B_VH 32768
#define B_VL 49152
#define SMEM_BYTES (65536 + 2 * 65536)   // 192 KB

#define C11 (1.0f / 2048.0f)

// convert raw chunk c (K and V) into fp16 buffer set dst
__device__ __forceinline__ void convert_chunk(uint32_t sb, uint32_t dst, int c) {
    const int row = c >> 4, f4 = c & 15;
    const uint32_t o8 = SWB(row, f4 >> 1) + ((uint32_t)(f4 & 1) << 3);
    {
        float4 v = lds128f(sb + O_RAWK + (uint32_t)c * 16);
        uint32_t h0 = packh2(v.x, v.y), h1 = packh2(v.z, v.w);
        float2 f0 = unpackh2(h0), f1 = unpackh2(h1);
        uint32_t l0_ = packh2((v.x - f0.x) * 2048.f, (v.y - f0.y) * 2048.f);
        uint32_t l1_ = packh2((v.z - f1.x) * 2048.f, (v.w - f1.y) * 2048.f);
        asm volatile("st.shared.v2.b32 [%0], {%1,%2};" :: "r"(dst + B_KH + o8), "r"(h0), "r"(h1));
        asm volatile("st.shared.v2.b32 [%0], {%1,%2};" :: "r"(dst + B_KL + o8), "r"(l0_), "r"(l1_));
    }
    {
        float4 v = lds128f(sb + O_RAWV + (uint32_t)c * 16);
        uint32_t h0 = packh2(v.x, v.y), h1 = packh2(v.z, v.w);
        float2 f0 = unpackh2(h0), f1 = unpackh2(h1);
        uint32_t l0_ = packh2((v.x - f0.x) * 2048.f, (v.y - f0.y) * 2048.f);
        uint32_t l1_ = packh2((v.z - f1.x) * 2048.f, (v.w - f1.y) * 2048.f);
        asm volatile("st.shared.v2.b32 [%0], {%1,%2};" :: "r"(dst + B_VH + o8), "r"(h0), "r"(h1));
        asm volatile("st.shared.v2.b32 [%0], {%1,%2};" :: "r"(dst + B_VL + o8), "r"(l0_), "r"(l1_));
    }
}

// issue cp.async for chunk c of (K,V) tile at kb/vb; one commit group
__device__ __forceinline__ void issue_chunk(uint32_t sb, int c,
                                            const float* kb, const float* vb,
                                            long rstride) {
    const int row = c >> 4, f4 = c & 15;
    cp_async16(sb + O_RAWK + (uint32_t)c * 16, kb + (long)row * rstride + (f4 << 2));
    cp_async16(sb + O_RAWV + (uint32_t)c * 16, vb + (long)row * rstride + (f4 << 2));
    CP_COMMIT();
}

// ---------------------------------------------------------------------------
// Kernel 1: scaled-split-fp16 mma.sync flash attention (noise-floor pruned).
// CTA = (q-tile of 128 rows, job). 8 warps x 16 rows. BLOCK_N = 128.
// GEMM1: hh + (h*lo2 + lo2*h)*2^-11            (ll term below noise floor)
// GEMM2: hh + (ph*vlo2 + plo2*vh)*2^-11        (ll term below noise floor)
// Pipelined convert/refill per j (R15 structure).
// ---------------------------------------------------------------------------
__global__ void __launch_bounds__(256) attn_kernel(
    const float* __restrict__ Q,
    const float* __restrict__ K,
    const float* __restrict__ V,
    float* __restrict__ out)
{
    extern __shared__ __align__(16) char smem_raw[];
    const uint32_t sb = smem_u32(smem_raw);
    const uint32_t buf0 = sb + O_BUF;
    const uint32_t buf1 = sb + O_BUF + 65536u;

    const int tid  = threadIdx.x;
    const int wid  = tid >> 5;
    const int lane = tid & 31;

    // ---- decode job ----
    const int job = blockIdx.y;
    int g, b, seg, hl;
    if (job < 32)      { g = 0; hl = job & 3;  seg = (job >> 2) & 3; b = job >> 4; }
    else if (job < 48) { int l = job - 32; g = 1; hl = l & 3; seg = (l >> 2) & 1; b = l >> 3; }
    else               { int l = job - 48; g = 2; hl = l & 3; seg = 0;            b = l >> 2; }
    const int r   = 1 << g;
    const int s   = 2048 << g;
    const int off = (g == 2) ? 2 : g;
    const int h   = g * 4 + hl;
    const long rstride = (long)r * ROWSTRIDE;
    const long segbase = ((long)b * NTOK + (long)seg * s + off) * ROWSTRIDE + h * 64;
    const long qbase   = segbase + (long)blockIdx.x * 128 * rstride;

    // ---- prologue: cp.async raw tile 0 (single group) ----
    {
        const float* kb = K + segbase;
        const float* vb = V + segbase;
        #pragma unroll
        for (int i = 0; i < 8; i++) {
            int c = tid + (i << 8);
            int row = c >> 4, f4 = c & 15;
            cp_async16(sb + O_RAWK + (uint32_t)c * 16, kb + (long)row * rstride + (f4 << 2));
            cp_async16(sb + O_RAWV + (uint32_t)c * 16, vb + (long)row * rstride + (f4 << 2));
        }
        CP_COMMIT();
    }

    // ---- stage Q (pre-scaled) into buf0.KH/KL, extract fragments ----
    const float qs = 0.125f * 1.4426950408889634f;
    #pragma unroll
    for (int i = 0; i < 8; i++) {
        int linear = tid + (i << 8);
        int row = linear >> 4, f4 = linear & 15;
        float4 v = *(const float4*)(Q + qbase + (long)row * rstride + (f4 << 2));
        v.x *= qs; v.y *= qs; v.z *= qs; v.w *= qs;
        uint32_t h0 = packh2(v.x, v.y), h1 = packh2(v.z, v.w);
        float2 f0 = unpackh2(h0), f1 = unpackh2(h1);
        uint32_t l0_ = packh2((v.x - f0.x) * 2048.f, (v.y - f0.y) * 2048.f);
        uint32_t l1_ = packh2((v.z - f1.x) * 2048.f, (v.w - f1.y) * 2048.f);
        uint32_t o8 = SWB(row, f4 >> 1) + ((uint32_t)(f4 & 1) << 3);
        asm volatile("st.shared.v2.b32 [%0], {%1,%2};" :: "r"(buf0 + B_KH + o8), "r"(h0), "r"(h1));
        asm volatile("st.shared.v2.b32 [%0], {%1,%2};" :: "r"(buf0 + B_KL + o8), "r"(l0_), "r"(l1_));
    }
    __syncthreads();

    uint32_t qfh[4][4], qfl[4][4];
    {
        uint32_t row = (uint32_t)(wid * 16 + (lane & 15));
        #pragma unroll
        for (int ks = 0; ks < 4; ks++) {
            uint32_t chunk = (uint32_t)(lane >> 4) + ((uint32_t)ks << 1);
            ldsm4(qfh[ks], buf0 + B_KH + SWB(row, chunk));
            ldsm4(qfl[ks], buf0 + B_KL + SWB(row, chunk));
        }
    }
    __syncthreads();   // all warps read Q before convert overwrites buf0

    // ---- wait raw tile0, convert to buf0, issue tile1 (per-chunk groups) ----
    CP_WAIT(0);
    {
        const float* kb = K + segbase + (long)128 * rstride;
        const float* vb = V + segbase + (long)128 * rstride;
        #pragma unroll
        for (int j = 0; j < 8; j++) {
            int c = tid + (j << 8);
            convert_chunk(sb, buf0, c);
            issue_chunk(sb, c, kb, vb, rstride);
        }
    }
    __syncthreads();   // buf0 ready

    float oacc[8][4];
    #pragma unroll
    for (int i = 0; i < 8; i++)
        #pragma unroll
        for (int e = 0; e < 4; e++) oacc[i][e] = 0.f;
    float lr0 = 0.f, lr1 = 0.f;

    for (int kt = 0; kt < 16; kt++) {
        const uint32_t cur = (kt & 1) ? buf1 : buf0;
        const uint32_t nxt = (kt & 1) ? buf0 : buf1;
        int nt = (kt + 2 < 16) ? (kt + 2) : 15;
        const float* kb2 = K + segbase + (long)(nt * 128) * rstride;
        const float* vb2 = V + segbase + (long)(nt * 128) * rstride;
        const bool doconv = (kt < 15);

        float ocor[8][4];
        #pragma unroll
        for (int i = 0; i < 8; i++)
            #pragma unroll
            for (int e = 0; e < 4; e++) ocor[i][e] = 0.f;

        // ping-pong GEMM1 accumulator block: [parity][acc 0..3][4]
        // acc 0,1 = hh(n-lo,n-hi); 2,3 = mid
        float ablk[2][4][4];

        // ---- GEMM1 block j=0 into ablk[0] ----
        #pragma unroll
        for (int a = 0; a < 4; a++)
            #pragma unroll
            for (int e = 0; e < 4; e++) ablk[0][a][e] = 0.f;
        {
            uint32_t row = (uint32_t)(lane & 15);
            #pragma unroll
            for (int ks = 0; ks < 4; ks++) {
                uint32_t chunk = (uint32_t)(lane >> 4) + ((uint32_t)ks << 1);
                uint32_t kh[4], kl[4];
                ldsm4(kh, cur + B_KH + SWB(row, chunk));
                ldsm4(kl, cur + B_KL + SWB(row, chunk));
                mma16816(ablk[0][0], qfh[ks], kh[0], kh[2], ablk[0][0]);
                mma16816(ablk[0][1], qfh[ks], kh[1], kh[3], ablk[0][1]);
                mma16816(ablk[0][2], qfh[ks], kl[0], kl[2], ablk[0][2]);
                mma16816(ablk[0][3], qfh[ks], kl[1], kl[3], ablk[0][3]);
                mma16816(ablk[0][2], qfl[ks], kh[0], kh[2], ablk[0][2]);
                mma16816(ablk[0][3], qfl[ks], kh[1], kh[3], ablk[0][3]);
            }
        }

        #pragma unroll
        for (int j = 0; j < 8; j++) {
            const int pj = j & 1, nj = pj ^ 1;

            // ---- softmax(j) from ablk[pj] ----
            uint32_t pfh[4], pfl[4];
            {
                float s0 = ablk[pj][0][0] + ablk[pj][2][0] * C11;
                float s1 = ablk[pj][0][1] + ablk[pj][2][1] * C11;
                float s2 = ablk[pj][0][2] + ablk[pj][2][2] * C11;
                float s3 = ablk[pj][0][3] + ablk[pj][2][3] * C11;
                float s4 = ablk[pj][1][0] + ablk[pj][3][0] * C11;
                float s5 = ablk[pj][1][1] + ablk[pj][3][1] * C11;
                float s6 = ablk[pj][1][2] + ablk[pj][3][2] * C11;
                float s7 = ablk[pj][1][3] + ablk[pj][3][3] * C11;
                float p0 = fast_exp2(s0), p1 = fast_exp2(s1);
                float p2 = fast_exp2(s2), p3 = fast_exp2(s3);
                float p4 = fast_exp2(s4), p5 = fast_exp2(s5);
                float p6 = fast_exp2(s6), p7 = fast_exp2(s7);
                lr0 += (p0 + p1) + (p4 + p5);
                lr1 += (p2 + p3) + (p6 + p7);
                pfh[0] = packh2(p0, p1);
                pfh[1] = packh2(p2, p3);
                pfh[2] = packh2(p4, p5);
                pfh[3] = packh2(p6, p7);
                float2 f;
                f = unpackh2(pfh[0]); pfl[0] = packh2((p0 - f.x) * 2048.f, (p1 - f.y) * 2048.f);
                f = unpackh2(pfh[1]); pfl[1] = packh2((p2 - f.x) * 2048.f, (p3 - f.y) * 2048.f);
                f = unpackh2(pfh[2]); pfl[2] = packh2((p4 - f.x) * 2048.f, (p5 - f.y) * 2048.f);
                f = unpackh2(pfh[3]); pfl[3] = packh2((p6 - f.x) * 2048.f, (p7 - f.y) * 2048.f);
            }

            // ---- zero ablk[nj] for GEMM1(j+1) ----
            if (j < 7) {
                #pragma unroll
                for (int a = 0; a < 4; a++)
                    #pragma unroll
                    for (int e = 0; e < 4; e++) ablk[nj][a][e] = 0.f;
            }

            // ---- fused: GEMM1(j+1) ks=i interleaved with GEMM2(j) dp=i ----
            uint32_t nrow = ((uint32_t)(j + 1) << 4) + (uint32_t)(lane & 15);
            uint32_t jr = ((uint32_t)j << 4) + (uint32_t)(lane & 7) + ((((uint32_t)lane >> 3) & 1u) << 3);
            #pragma unroll
            for (int i = 0; i < 4; i++) {
                uint32_t chunk = (uint32_t)(lane >> 4) + ((uint32_t)i << 1);
                if (j < 7) {
                    uint32_t kh[4], kl[4];
                    ldsm4(kh, cur + B_KH + SWB(nrow, chunk));
                    ldsm4(kl, cur + B_KL + SWB(nrow, chunk));
                    mma16816(ablk[nj][0], qfh[i], kh[0], kh[2], ablk[nj][0]);
                    mma16816(ablk[nj][1], qfh[i], kh[1], kh[3], ablk[nj][1]);
                    mma16816(ablk[nj][2], qfh[i], kl[0], kl[2], ablk[nj][2]);
                    mma16816(ablk[nj][3], qfh[i], kl[1], kl[3], ablk[nj][3]);
                    mma16816(ablk[nj][2], qfl[i], kh[0], kh[2], ablk[nj][2]);
                    mma16816(ablk[nj][3], qfl[i], kh[1], kh[3], ablk[nj][3]);
                }
                {
                    uint32_t vh[4], vl[4];
                    ldsm4t(vh, cur + B_VH + SWB(jr, chunk));
                    ldsm4t(vl, cur + B_VL + SWB(jr, chunk));
                    mma16816(oacc[2*i],   pfh, vh[0], vh[1], oacc[2*i]);
                    mma16816(oacc[2*i+1], pfh, vh[2], vh[3], oacc[2*i+1]);
                    mma16816(ocor[2*i],   pfh, vl[0], vl[1], ocor[2*i]);
                    mma16816(ocor[2*i+1], pfh, vl[2], vl[3], ocor[2*i+1]);
                    mma16816(ocor[2*i],   pfl, vh[0], vh[1], ocor[2*i]);
                    mma16816(ocor[2*i+1], pfl, vh[2], vh[3], ocor[2*i+1]);
                }
            }

            // ---- interleaved: convert chunk j of tile kt+1, refill tile kt+2 ----
            if (doconv) {
                CP_WAIT(7);                       // oldest group = chunk j of tile kt+1
                int c = tid + (j << 8);
                convert_chunk(sb, nxt, c);
                issue_chunk(sb, c, kb2, vb2, rstride);
            }
        }

        // fold correction into main accumulator
        #pragma unroll
        for (int i = 0; i < 8; i++)
            #pragma unroll
            for (int e = 0; e < 4; e++)
                oacc[i][e] = fmaf(ocor[i][e], C11, oacc[i][e]);

        __syncthreads();   // all warps done with cur before next iter overwrites it
    }
    CP_WAIT(0);            // retire trailing dummy groups before exit

    // ---- epilogue: reduce l across quad, normalize, write ----
    lr0 += __shfl_xor_sync(0xffffffffu, lr0, 1);
    lr0 += __shfl_xor_sync(0xffffffffu, lr0, 2);
    lr1 += __shfl_xor_sync(0xffffffffu, lr1, 1);
    lr1 += __shfl_xor_sync(0xffffffffu, lr1, 2);
    const float inv0 = 1.f / lr0;
    const float inv1 = 1.f / lr1;

    const int gq = lane >> 2, t4 = lane & 3;
    float* r0p = out + qbase + (long)(wid * 16 + gq) * rstride;
    float* r1p = out + qbase + (long)(wid * 16 + gq + 8) * rstride;
    #pragma unroll
    for (int dt = 0; dt < 8; dt++) {
        float2 w0 = make_float2(oacc[dt][0] * inv0, oacc[dt][1] * inv0);
        float2 w1 = make_float2(oacc[dt][2] * inv1, oacc[dt][3] * inv1);
        *(float2*)(r0p + dt * 8 + 2 * t4) = w0;
        *(float2*)(r1p + dt * 8 + 2 * t4) = w1;
    }
}

// ---------------------------------------------------------------------------
// Kernel 2a: per-(b,h) partial sums over covered positions (8 parts).
// ---------------------------------------------------------------------------
__global__ void __launch_bounds__(512) denom_partial(const float* __restrict__ out)
{
    __shared__ float red[512];
    const int bh   = blockIdx.x;      // 0..23
    const int part = blockIdx.y;      // 0..7
    const int b  = bh / HEADS;
    const int h  = bh % HEADS;
    const int g  = h >> 2;
    const int r  = 1 << g;
    const int off = (g == 2) ? 2 : g;

    const int tid   = threadIdx.x;
    const int d     = tid & 63;
    const int slice = tid >> 6;            // 0..7
    const int lanei = part * 8 + slice;    // 0..63
    const int count = NTOK >> g;

    const float* p = out + ((long)b * NTOK + off) * ROWSTRIDE + h * 64 + d;
    float acc = 0.f;
    for (int t = lanei; t < count; t += 64)
        acc += p[(long)t * r * ROWSTRIDE];

    red[tid] = acc;
    __syncthreads();
    if (slice == 0) {
        float sum = red[d];
        #pragma unroll
        for (int k = 1; k < 8; k++) sum += red[k * 64 + d];
        g_partial[(bh * 8 + part) * 64 + d] = sum;
    }
}

// ---------------------------------------------------------------------------
// Kernel 2b: combine partials into g_denom.
// ---------------------------------------------------------------------------
__global__ void __launch_bounds__(64) denom_combine()
{
    const int bh = blockIdx.x;
    const int d  = threadIdx.x;
    float s = 0.f;
    #pragma unroll
    for (int p = 0; p < 8; p++)
        s += g_partial[(bh * 8 + p) * 64 + d];
    g_denom[bh * 64 + d] = s;
}

// ---------------------------------------------------------------------------
// Kernel 3: final normalize + zero uncovered positions (float4).
// ---------------------------------------------------------------------------
__global__ void __launch_bounds__(256) norm_kernel(float4* __restrict__ out4)
{
    const long total4 = (long)2 * NTOK * HEADS * 16;
    long i4 = (long)blockIdx.x * 256 + threadIdx.x;
    if (i4 >= total4) return;

    int  dq = (int)(i4 & 15);
    long t = i4 >> 4;
    int  h = (int)(t % HEADS); t /= HEADS;
    int  n = (int)(t % NTOK);
    int  b = (int)(t / NTOK);

    int g   = h >> 2;
    int r   = 1 << g;
    int off = (g == 2) ? 2 : g;

    float4 v = make_float4(0.f, 0.f, 0.f, 0.f);
    if ((n & (r - 1)) == off) {
        float4 x = out4[i4];
        const float* dn = g_denom + (b * HEADS + h) * 64 + dq * 4;
        v.x = x.x / (dn[0] * 3.0f);
        v.y = x.y / (dn[1] * 3.0f);
        v.z = x.z / (dn[2] * 3.0f);
        v.w = x.w / (dn[3] * 3.0f);
    }
    out4[i4] = v;
}

// ---------------------------------------------------------------------------
extern "C" void kernel_launch(void* const* d_in, const int* in_sizes, int n_in,
                              void* d_out, int out_size)
{
    const float* Q = (const float*)d_in[0];
    const float* K = (const float*)d_in[1];
    const float* V = (const float*)d_in[2];
    float* out = (float*)d_out;

    static int configured = 0;
    if (!configured) {
        cudaFuncSetAttribute(attn_kernel,
                             cudaFuncAttributeMaxDynamicSharedMemorySize, SMEM_BYTES);
        configured = 1;
    }

    attn_kernel<<<dim3(16, 56), 256, SMEM_BYTES>>>(Q, K, V, out);
    denom_partial<<<dim3(2 * HEADS, 8), 512>>>(out);
    denom_combine<<<2 * HEADS, 64>>>();

    const long total4 = (long)2 * NTOK * HEADS * 16;
    int blocks = (int)((total4 + 255) / 256);
    norm_kernel<<<blocks, 256>>>((float4*)out);
}